// round 3
// baseline (speedup 1.0000x reference)
#include <cuda_runtime.h>
#include <cuda_bf16.h>

// ---------------------------------------------------------------------------
// VQEmbedding: N=131072 pixels (B=32,H=64,W=64), D=64, K=1024 codes.
// Replicates reference fp32 arithmetic exactly:
//   G_nk = sum_d x*w (fp32 FMA, seq d) ; d_nk = rn( rn(S_n + T_k) - 2*G_nk )
//   argmin with lowest-index tie-break on the quantized distances.
// Output layout (float32): [ out : 8388608 | loss : 1 | indices : 131072 ]
// ---------------------------------------------------------------------------

#define TN 128      // pixels per block
#define TK 128      // codes per smem chunk
#define PAD 132     // smem row stride (floats)
#define NUM_K 1024
#define D 64
#define OUT_ELEMS 8388608   // 32*64*64*64
#define LOSS_OFF  8388608
#define IDX_OFF   8388609

__device__ __align__(16) float  g_T[NUM_K];          // sum(w_k^2)
__device__ __align__(16) float  g_wT[D * NUM_K];     // w transposed [d][k]
__device__ double g_loss_sum;

__device__ __forceinline__ unsigned long long pack2(float x, float y) {
    unsigned long long r;
    asm("mov.b64 %0, {%1, %2};" : "=l"(r)
        : "r"(__float_as_uint(x)), "r"(__float_as_uint(y)));
    return r;
}
__device__ __forceinline__ void unpack2(unsigned long long p, float &x, float &y) {
    unsigned int a, b;
    asm("mov.b64 {%0, %1}, %2;" : "=r"(a), "=r"(b) : "l"(p));
    x = __uint_as_float(a); y = __uint_as_float(b);
}
#define FMA2(d, a, b, c) \
    asm("fma.rn.f32x2 %0, %1, %2, %3;" : "=l"(d) : "l"(a), "l"(b), "l"(c))

// ---------------------------------------------------------------------------
// Prep: zero loss accumulator, transpose weight, compute T_k = sum(w^2)
// (square rounded separately, then summed, mirroring w**2 followed by sum)
// ---------------------------------------------------------------------------
__global__ void vq_prep(const float* __restrict__ w) {
    int t = blockIdx.x * blockDim.x + threadIdx.x;   // 65536 threads
    if (t == 0) g_loss_sum = 0.0;
    if (t < D * NUM_K) {
        int k = t >> 6, d = t & 63;                  // coalesced read of w
        g_wT[d * NUM_K + k] = w[t];
    }
    if (t < NUM_K) {
        const float* wr = w + t * D;
        float s = 0.f;
        #pragma unroll
        for (int j = 0; j < D; j++) {
            float sq = __fmul_rn(wr[j], wr[j]);
            s = __fadd_rn(s, sq);
        }
        g_T[t] = s;
    }
}

// ---------------------------------------------------------------------------
// Main: per-block 128 pixels x 1024 codes (f32x2 FFMA GEMM) + exact-formula
//       argmin + scatter-out + loss partial
// ---------------------------------------------------------------------------
extern __shared__ float smem[];

__global__ __launch_bounds__(256, 2)
void vq_main(const float* __restrict__ x, const float* __restrict__ w,
             float* __restrict__ out) {
    float* As = smem;                         // [64][PAD] pixels   (x[d][n])
    float* Ws = smem + D * PAD;               // [64][PAD] codes    (w[d][k])
    float* Ss = smem + 2 * D * PAD;           // [128]  S_n = sum x^2
    int*   bestk_s = (int*)(Ss + TN);         // [128]
    float* red = (float*)(bestk_s + TN);      // [8]

    const int tid = threadIdx.x;
    const int tx = tid & 15;        // k-dim (16 lanes within half-warp)
    const int ty = tid >> 4;        // n-dim (16 rows)
    const int n0 = blockIdx.x * TN;
    const int b  = n0 >> 12;        // 4096 pixels per batch image
    const int hw0 = n0 & 4095;
    const float* xb = x + ((size_t)b << 18);

    // Load A tile: As[d][nl] = x[b, d, hw0+nl]  (coalesced along w)
    for (int e = tid; e < TN * D; e += 256) {
        int nl = e & 127, d = e >> 7;
        As[d * PAD + nl] = xb[(d << 12) + hw0 + nl];
    }
    __syncthreads();

    // S_n = sum_d x^2 (square rounded, then fp32 add; per-pixel)
    if (tid < TN) {
        float s = 0.f;
        #pragma unroll
        for (int d = 0; d < D; d++) {
            float v = As[d * PAD + tid];
            float sq = __fmul_rn(v, v);
            s = __fadd_rn(s, sq);
        }
        Ss[tid] = s;
    }
    __syncthreads();

    float s8[8];
    #pragma unroll
    for (int i = 0; i < 8; i++) s8[i] = Ss[(ty << 3) + i];

    float bestv[8];
    int   besti[8];
    #pragma unroll
    for (int i = 0; i < 8; i++) { bestv[i] = 3.4e38f; besti[i] = 0; }

    #pragma unroll 1
    for (int kc = 0; kc < NUM_K; kc += TK) {
        __syncthreads();   // previous chunk consumed
        for (int e = tid; e < TK * D; e += 256) {
            int kk = e & 127, d = e >> 7;
            Ws[d * PAD + kk] = g_wT[(d << 10) + kc + kk];
        }
        __syncthreads();

        // G accumulators start at 0
        unsigned long long acc[32];
        #pragma unroll
        for (int i = 0; i < 32; i++) acc[i] = 0ull;

        #pragma unroll 4
        for (int d = 0; d < D; d++) {
            const float* Ar = As + d * PAD + (ty << 3);
            const float* Wr = Ws + d * PAD + (tx << 3);
            float4 wa = *(const float4*)Wr;
            float4 wb = *(const float4*)(Wr + 4);
            unsigned long long wp0 = pack2(wa.x, wa.y);
            unsigned long long wp1 = pack2(wa.z, wa.w);
            unsigned long long wp2 = pack2(wb.x, wb.y);
            unsigned long long wp3 = pack2(wb.z, wb.w);
            float4 aa = *(const float4*)Ar;
            float4 ab = *(const float4*)(Ar + 4);
            float av[8] = {aa.x, aa.y, aa.z, aa.w, ab.x, ab.y, ab.z, ab.w};
            #pragma unroll
            for (int i = 0; i < 8; i++) {
                unsigned long long ap = pack2(av[i], av[i]);
                FMA2(acc[i * 4 + 0], ap, wp0, acc[i * 4 + 0]);
                FMA2(acc[i * 4 + 1], ap, wp1, acc[i * 4 + 1]);
                FMA2(acc[i * 4 + 2], ap, wp2, acc[i * 4 + 2]);
                FMA2(acc[i * 4 + 3], ap, wp3, acc[i * 4 + 3]);
            }
        }

        // Exact reference formula: d = rn( rn(S+T) - 2G ), running argmin.
        // Ascending k with strict < keeps the lowest index on exact ties.
        const int kb = kc + (tx << 3);
        float tk[8];
        {
            float4 t4a = *(const float4*)(g_T + kb);
            float4 t4b = *(const float4*)(g_T + kb + 4);
            tk[0]=t4a.x; tk[1]=t4a.y; tk[2]=t4a.z; tk[3]=t4a.w;
            tk[4]=t4b.x; tk[5]=t4b.y; tk[6]=t4b.z; tk[7]=t4b.w;
        }
        #pragma unroll
        for (int i = 0; i < 8; i++) {
            float Si = s8[i];
            #pragma unroll
            for (int j = 0; j < 4; j++) {
                float G0, G1;
                unpack2(acc[i * 4 + j], G0, G1);
                float u0 = __fadd_rn(Si, tk[2 * j]);
                float u1 = __fadd_rn(Si, tk[2 * j + 1]);
                float d0 = __fmaf_rn(-2.f, G0, u0);   // rn(u0 - 2*G0)
                float d1 = __fmaf_rn(-2.f, G1, u1);
                int k0 = kb + j * 2;
                if (d0 < bestv[i]) { bestv[i] = d0; besti[i] = k0; }
                if (d1 < bestv[i]) { bestv[i] = d1; besti[i] = k0 + 1; }
            }
        }
    }

    // reduce over the 16 tx lanes; smaller index wins exact ties
    #pragma unroll
    for (int i = 0; i < 8; i++) {
        float v = bestv[i]; int bi = besti[i];
        #pragma unroll
        for (int off = 8; off; off >>= 1) {
            float ov = __shfl_xor_sync(0xffffffffu, v, off);
            int   oi = __shfl_xor_sync(0xffffffffu, bi, off);
            if (ov < v || (ov == v && oi < bi)) { v = ov; bi = oi; }
        }
        if (tx == 0) bestk_s[(ty << 3) + i] = bi;
    }
    __syncthreads();

    // gather selected codewords into Ws for coalesced scatter
    if (tid < TN) {
        int k = bestk_s[tid];
        const float4* src = (const float4*)(w + (k << 6));
        #pragma unroll
        for (int j = 0; j < 16; j++) {
            float4 v = src[j];
            int d = j * 4;
            Ws[(d + 0) * PAD + tid] = v.x;
            Ws[(d + 1) * PAD + tid] = v.y;
            Ws[(d + 2) * PAD + tid] = v.z;
            Ws[(d + 3) * PAD + tid] = v.w;
        }
    }
    __syncthreads();

    // scatter to NCHW (coalesced along w), accumulate loss partial
    const size_t ob = ((size_t)b << 18);
    float lsum = 0.f;
    for (int e = tid; e < TN * D; e += 256) {
        int nl = e & 127, d = e >> 7;
        float wv = Ws[d * PAD + nl];
        float xv = As[d * PAD + nl];
        out[ob + (d << 12) + hw0 + nl] = wv;
        float df = xv - wv;
        lsum += df * df;
    }
    if (tid < TN) out[IDX_OFF + n0 + tid] = (float)bestk_s[tid];

    #pragma unroll
    for (int off = 16; off; off >>= 1)
        lsum += __shfl_xor_sync(0xffffffffu, lsum, off);
    if ((tid & 31) == 0) red[tid >> 5] = lsum;
    __syncthreads();
    if (tid == 0) {
        float s = 0.f;
        #pragma unroll
        for (int i = 0; i < 8; i++) s += red[i];
        atomicAdd(&g_loss_sum, (double)s);
    }
}

__global__ void vq_fin(float* __restrict__ out) {
    if (threadIdx.x == 0)
        out[LOSS_OFF] = (float)(1.25 * g_loss_sum / (double)OUT_ELEMS);
}

// ---------------------------------------------------------------------------
extern "C" void kernel_launch(void* const* d_in, const int* in_sizes, int n_in,
                              void* d_out, int out_size) {
    const float* x = (const float*)d_in[0];   // [32,64,64,64] f32
    const float* w = (const float*)d_in[1];   // [1024,64] f32
    float* out = (float*)d_out;

    const int SMEM_BYTES = (2 * D * PAD) * 4 + TN * 4 + TN * 4 + 8 * 4;
    cudaFuncSetAttribute(vq_main, cudaFuncAttributeMaxDynamicSharedMemorySize,
                         SMEM_BYTES);

    vq_prep<<<256, 256>>>(w);
    vq_main<<<1024, 256, SMEM_BYTES>>>(x, w, out);
    vq_fin<<<1, 32>>>(out);
}

// round 4
// speedup vs baseline: 1.1025x; 1.1025x over previous
#include <cuda_runtime.h>
#include <cuda_bf16.h>

// ---------------------------------------------------------------------------
// VQEmbedding: N=131072 pixels (B=32,H=64,W=64), D=64, K=1024 codes.
// Exact reference fp32 arithmetic:
//   G_nk = sum_d x*w (fp32 FMA, seq d) ; d_nk = rn( rn(S_n + T_k) - 2*G_nk )
//   argmin with lowest-index tie-break.
// Output layout (float32): [ out : 8388608 | loss : 1 | indices : 131072 ]
// ---------------------------------------------------------------------------

#define TN 128
#define TK 128
#define PAD 132            // smem row stride in floats (16B-aligned rows)
#define NUM_K 1024
#define D 64
#define WOFF (D * PAD)     // one W buffer, in floats
#define OUT_ELEMS 8388608
#define LOSS_OFF  8388608
#define IDX_OFF   8388609

__device__ __align__(16) float  g_T[NUM_K];          // sum(w_k^2), seq order
__device__ __align__(16) float  g_wT[D * NUM_K];     // w transposed [d][k]
__device__ double g_loss_sum;

typedef unsigned long long ull;

__device__ __forceinline__ ull pack2(float x, float y) {
    ull r;
    asm("mov.b64 %0, {%1, %2};" : "=l"(r)
        : "r"(__float_as_uint(x)), "r"(__float_as_uint(y)));
    return r;
}
__device__ __forceinline__ void unpack2(ull p, float &x, float &y) {
    unsigned int a, b;
    asm("mov.b64 {%0, %1}, %2;" : "=r"(a), "=r"(b) : "l"(p));
    x = __uint_as_float(a); y = __uint_as_float(b);
}
#define FMA2(d, a, b, c) \
    asm("fma.rn.f32x2 %0, %1, %2, %3;" : "=l"(d) : "l"(a), "l"(b), "l"(c))

// ---------------------------------------------------------------------------
// Prep: 16 blocks, each transposes a 64-code slab of w through smem and
// computes T_k = sum_d w^2 (rounded square, sequential fp32 adds).
// ---------------------------------------------------------------------------
__global__ __launch_bounds__(256)
void vq_prep(const float* __restrict__ w) {
    __shared__ float s[64][65];
    const int t = threadIdx.x;
    const int kb = blockIdx.x * 64;
    if (blockIdx.x == 0 && t == 0) g_loss_sum = 0.0;

    // load w[kb+k][dq..dq+15], coalesced
    {
        int k = t >> 2, dq = (t & 3) << 4;
        const float4* src = (const float4*)(w + (kb + k) * D + dq);
        float4 v0 = src[0], v1 = src[1], v2 = src[2], v3 = src[3];
        s[dq+ 0][k] = v0.x; s[dq+ 1][k] = v0.y; s[dq+ 2][k] = v0.z; s[dq+ 3][k] = v0.w;
        s[dq+ 4][k] = v1.x; s[dq+ 5][k] = v1.y; s[dq+ 6][k] = v1.z; s[dq+ 7][k] = v1.w;
        s[dq+ 8][k] = v2.x; s[dq+ 9][k] = v2.y; s[dq+10][k] = v2.z; s[dq+11][k] = v2.w;
        s[dq+12][k] = v3.x; s[dq+13][k] = v3.y; s[dq+14][k] = v3.z; s[dq+15][k] = v3.w;
    }
    __syncthreads();

    // write g_wT[d][kb+kq .. +16] (16B stores)
    {
        int d = t >> 2, kq = (t & 3) << 4;
        float4* dst = (float4*)(g_wT + d * NUM_K + kb + kq);
        #pragma unroll
        for (int j = 0; j < 4; j++) {
            float4 o;
            o.x = s[d][kq + 4*j + 0]; o.y = s[d][kq + 4*j + 1];
            o.z = s[d][kq + 4*j + 2]; o.w = s[d][kq + 4*j + 3];
            dst[j] = o;
        }
    }

    // T_k, sequential over d
    if (t < 64) {
        float acc = 0.f;
        #pragma unroll
        for (int d = 0; d < D; d++) {
            float v = s[d][t];
            acc = __fadd_rn(acc, __fmul_rn(v, v));
        }
        g_T[kb + t] = acc;
    }
}

// ---------------------------------------------------------------------------
// cp.async stage of one 128x64 W chunk (g_wT slab) into a smem buffer.
// ---------------------------------------------------------------------------
__device__ __forceinline__ void stage_chunk(float* dst, const float* src, int tid) {
    #pragma unroll
    for (int i = 0; i < 8; i++) {
        int idx = tid + i * 256;            // float4 index, 2048 total
        int d = idx >> 5;
        int kk = (idx & 31) << 2;
        unsigned saddr = (unsigned)__cvta_generic_to_shared(dst + d * PAD + kk);
        const float* g = src + d * NUM_K + kk;
        asm volatile("cp.async.cg.shared.global [%0], [%1], 16;\n"
                     :: "r"(saddr), "l"(g));
    }
    asm volatile("cp.async.commit_group;\n" ::: "memory");
}
__device__ __forceinline__ void stage_wait() {
    asm volatile("cp.async.wait_group 0;\n" ::: "memory");
}

// ---------------------------------------------------------------------------
// Main kernel: 1024 blocks x 256 threads, occ 1.
// Thread grid 16(tx=k) x 16(ty=n); per-thread 8n x 8k; accs paired over n.
// ---------------------------------------------------------------------------
extern __shared__ float smem[];

__global__ __launch_bounds__(256, 1)
void vq_main(const float* __restrict__ x, const float* __restrict__ w,
             float* __restrict__ out) {
    float* As  = smem;                       // [64][PAD]
    float* Wb  = smem + WOFF;                // 2 x [64][PAD]
    float* Ss  = smem + 3 * WOFF;            // [128]
    int*   bestk_s = (int*)(Ss + TN);        // [128]
    float* red = (float*)(bestk_s + TN);     // [8]

    const int tid = threadIdx.x;
    const int tx = tid & 15;
    const int ty = tid >> 4;
    const int n0 = blockIdx.x * TN;
    const int b  = n0 >> 12;
    const int hw0 = n0 & 4095;
    const float* xb = x + ((size_t)b << 18);

    // stage chunk 0 first so it overlaps the A-tile load
    stage_chunk(Wb, g_wT, tid);

    for (int e = tid; e < TN * D; e += 256) {
        int nl = e & 127, d = e >> 7;
        As[d * PAD + nl] = xb[(d << 12) + hw0 + nl];
    }
    __syncthreads();

    if (tid < TN) {
        float s = 0.f;
        #pragma unroll
        for (int d = 0; d < D; d++) {
            float v = As[d * PAD + tid];
            s = __fadd_rn(s, __fmul_rn(v, v));
        }
        Ss[tid] = s;
    }
    stage_wait();
    __syncthreads();

    float s8[8];
    #pragma unroll
    for (int i = 0; i < 8; i++) s8[i] = Ss[(ty << 3) + i];

    float bestv[8];
    int   besti[8];
    #pragma unroll
    for (int i = 0; i < 8; i++) { bestv[i] = 3.4e38f; besti[i] = 0; }

    #pragma unroll 1
    for (int c = 0; c < 8; c++) {
        const int kc = c << 7;
        const float* cur = Wb + (c & 1) * WOFF;
        if (c < 7)
            stage_chunk(Wb + ((c + 1) & 1) * WOFF, g_wT + kc + TK, tid);

        // prefetch T_k for this chunk (latency hidden by the d-loop)
        const int kb = kc + (tx << 3);
        float4 t4a = *(const float4*)(g_T + kb);
        float4 t4b = *(const float4*)(g_T + kb + 4);

        ull acc[32];
        #pragma unroll
        for (int i = 0; i < 32; i++) acc[i] = 0ull;

        const float* Ar0 = As + (ty << 3);
        const float* Wr0 = cur + (tx << 3);
        #pragma unroll 16
        for (int d = 0; d < D; d++) {
            const float* Ar = Ar0 + d * PAD;
            const float* Wr = Wr0 + d * PAD;
            // A pairs: free (register pairs straight from LDS.128)
            ulonglong2 a01 = ((const ulonglong2*)Ar)[0];  // (n0,n1),(n2,n3)
            ulonglong2 a23 = ((const ulonglong2*)Ar)[1];  // (n4,n5),(n6,n7)
            ull ap0 = a01.x, ap1 = a01.y, ap2 = a23.x, ap3 = a23.y;
            float4 wa = *(const float4*)Wr;
            float4 wb2 = *(const float4*)(Wr + 4);
            ull wd[8];
            wd[0] = pack2(wa.x,  wa.x);  wd[1] = pack2(wa.y,  wa.y);
            wd[2] = pack2(wa.z,  wa.z);  wd[3] = pack2(wa.w,  wa.w);
            wd[4] = pack2(wb2.x, wb2.x); wd[5] = pack2(wb2.y, wb2.y);
            wd[6] = pack2(wb2.z, wb2.z); wd[7] = pack2(wb2.w, wb2.w);
            #pragma unroll
            for (int k = 0; k < 8; k++) {
                FMA2(acc[k * 4 + 0], ap0, wd[k], acc[k * 4 + 0]);
                FMA2(acc[k * 4 + 1], ap1, wd[k], acc[k * 4 + 1]);
                FMA2(acc[k * 4 + 2], ap2, wd[k], acc[k * 4 + 2]);
                FMA2(acc[k * 4 + 3], ap3, wd[k], acc[k * 4 + 3]);
            }
        }

        // exact reference scoring: d = rn( rn(S+T) - 2G ), running argmin
        float tk[8] = {t4a.x, t4a.y, t4a.z, t4a.w, t4b.x, t4b.y, t4b.z, t4b.w};
        #pragma unroll
        for (int k = 0; k < 8; k++) {
            float T = tk[k];
            int kg = kb + k;
            #pragma unroll
            for (int np = 0; np < 4; np++) {
                float G0, G1;
                unpack2(acc[k * 4 + np], G0, G1);
                float u0 = __fadd_rn(s8[2*np],     T);
                float u1 = __fadd_rn(s8[2*np + 1], T);
                float d0 = __fmaf_rn(-2.f, G0, u0);
                float d1 = __fmaf_rn(-2.f, G1, u1);
                if (d0 < bestv[2*np])     { bestv[2*np]     = d0; besti[2*np]     = kg; }
                if (d1 < bestv[2*np + 1]) { bestv[2*np + 1] = d1; besti[2*np + 1] = kg; }
            }
        }

        if (c < 7) { stage_wait(); __syncthreads(); }
    }

    // reduce across the 16 tx lanes; lower index wins exact ties
    #pragma unroll
    for (int i = 0; i < 8; i++) {
        float v = bestv[i]; int bi = besti[i];
        #pragma unroll
        for (int off = 8; off; off >>= 1) {
            float ov = __shfl_xor_sync(0xffffffffu, v, off);
            int   oi = __shfl_xor_sync(0xffffffffu, bi, off);
            if (ov < v || (ov == v && oi < bi)) { v = ov; bi = oi; }
        }
        if (tx == 0) bestk_s[(ty << 3) + i] = bi;
    }
    __syncthreads();

    // gather chosen codewords (reuse W buffer 0) for coalesced NCHW scatter
    if (tid < TN) {
        int k = bestk_s[tid];
        const float4* src = (const float4*)(w + (k << 6));
        #pragma unroll
        for (int j = 0; j < 16; j++) {
            float4 v = src[j];
            int d = j * 4;
            Wb[(d + 0) * PAD + tid] = v.x;
            Wb[(d + 1) * PAD + tid] = v.y;
            Wb[(d + 2) * PAD + tid] = v.z;
            Wb[(d + 3) * PAD + tid] = v.w;
        }
    }
    __syncthreads();

    const size_t ob = ((size_t)b << 18);
    float lsum = 0.f;
    for (int e = tid; e < TN * D; e += 256) {
        int nl = e & 127, d = e >> 7;
        float wv = Wb[d * PAD + nl];
        float xv = As[d * PAD + nl];
        out[ob + (d << 12) + hw0 + nl] = wv;
        float df = xv - wv;
        lsum += df * df;
    }
    if (tid < TN) out[IDX_OFF + n0 + tid] = (float)bestk_s[tid];

    #pragma unroll
    for (int off = 16; off; off >>= 1)
        lsum += __shfl_xor_sync(0xffffffffu, lsum, off);
    if ((tid & 31) == 0) red[tid >> 5] = lsum;
    __syncthreads();
    if (tid == 0) {
        float s = 0.f;
        #pragma unroll
        for (int i = 0; i < 8; i++) s += red[i];
        atomicAdd(&g_loss_sum, (double)s);
    }
}

__global__ void vq_fin(float* __restrict__ out) {
    if (threadIdx.x == 0)
        out[LOSS_OFF] = (float)(1.25 * g_loss_sum / (double)OUT_ELEMS);
}

// ---------------------------------------------------------------------------
extern "C" void kernel_launch(void* const* d_in, const int* in_sizes, int n_in,
                              void* d_out, int out_size) {
    const float* x = (const float*)d_in[0];   // [32,64,64,64] f32
    const float* w = (const float*)d_in[1];   // [1024,64] f32
    float* out = (float*)d_out;

    const int SMEM_BYTES = (3 * WOFF) * 4 + TN * 4 + TN * 4 + 8 * 4;
    cudaFuncSetAttribute(vq_main, cudaFuncAttributeMaxDynamicSharedMemorySize,
                         SMEM_BYTES);

    vq_prep<<<16, 256>>>(w);
    vq_main<<<1024, 256, SMEM_BYTES>>>(x, w, out);
    vq_fin<<<1, 32>>>(out);
}